// round 7
// baseline (speedup 1.0000x reference)
#include <cuda_runtime.h>
#include <cuda_bf16.h>

#define IMG_H 384
#define IMG_W 640
#define N_PLANES 96            // 32 * 3
#define WIN 11
#define HALO 5
#define OUT_W_TILE 246
#define NX 3                   // 246 + 246 + 148 = 640
#define NY 3
#define ROWS_PER_BLK (IMG_H / NY)       // 128
#define CHUNK 8
#define NCHUNKS (ROWS_PER_BLK / CHUNK)  // 16
#define NTHREADS 256

// SMEM: two packed-ull arrays, CHUNK rows x VS2 ull each.
//   A01 : (Sum p, Sum t)           packed f32x2
//   A234: (Sum p^2+t^2, Sum p*t)   packed f32x2
// VS2=258 ull/row: 2*VS2 = 516 == 4 (mod 32) -> 8-lane LDS.128 phases hit
// 8 distinct 4-bank groups -> conflict-free.
#define VS2 258
#define A234_U (CHUNK * VS2)                 // ull offset of A234
#define SMEM_BYTES (2 * CHUNK * VS2 * 8 + 256)   // 33,280 B

#define C1F 1e-4f
#define C2F 9e-4f
#define N_BLOCKS (NX * NY * N_PLANES)  // 864

__device__ float g_partials[N_BLOCKS];
__device__ unsigned int g_count = 0;

// ---- packed f32x2 helpers (Blackwell FFMA2 path) ----
__device__ __forceinline__ unsigned long long pk2(float lo, float hi) {
    unsigned long long r;
    asm("mov.b64 %0, {%1, %2};" : "=l"(r) : "f"(lo), "f"(hi));
    return r;
}
__device__ __forceinline__ void upk2(unsigned long long v, float& lo, float& hi) {
    asm("mov.b64 {%0, %1}, %2;" : "=f"(lo), "=f"(hi) : "l"(v));
}
__device__ __forceinline__ unsigned long long add2(unsigned long long a, unsigned long long b) {
    unsigned long long r;
    asm("add.rn.f32x2 %0, %1, %2;" : "=l"(r) : "l"(a), "l"(b));
    return r;
}
__device__ __forceinline__ unsigned long long fma2(unsigned long long a, unsigned long long b,
                                                   unsigned long long c) {
    unsigned long long r;
    asm("fma.rn.f32x2 %0, %1, %2, %3;" : "=l"(r) : "l"(a), "l"(b), "l"(c));
    return r;
}
#define NEG1_X2 0xBF800000BF800000ULL   // packed (-1.0f, -1.0f)

__global__ __launch_bounds__(NTHREADS, 3)
void ssim_main(const float* __restrict__ pred, const float* __restrict__ targ,
               float* __restrict__ out) {
    extern __shared__ float smem[];
    unsigned long long* __restrict__ sm64 =
        reinterpret_cast<unsigned long long*>(smem);

    const int b = blockIdx.x;
    const int xt = b % NX;
    const int yt = (b / NX) % NY;
    const int plane = b / (NX * NY);

    const int x0 = xt * OUT_W_TILE;
    const int outw = min(OUT_W_TILE, IMG_W - x0);   // 246 or 148
    const int inw = outw + 2 * HALO;                // 256 or 158
    const int r0 = yt * ROWS_PER_BLK;

    const size_t poff = (size_t)plane * (IMG_H * IMG_W);
    const float* __restrict__ P = pred + poff;
    const float* __restrict__ T = targ + poff;

    // ---------- vertical-pass identity ----------
    const int c = threadIdx.x;               // buffer column
    const int gx = x0 - HALO + c;            // global column
    const bool cvalid = (c < inw);
    const bool colin = cvalid && (gx >= 0) && (gx < IMG_W);

    unsigned long long vs01 = 0ULL;          // packed (sum p, sum t)
    float vs23 = 0.f;                        // sum (p*p + t*t)
    float vs4 = 0.f;                         // sum (p*t)

    #pragma unroll
    for (int k = -HALO; k < HALO; ++k) {
        const int rr = r0 + k;
        float p = 0.f, t = 0.f;
        if (colin && rr >= 0 && rr < IMG_H) {
            p = P[rr * IMG_W + gx];
            t = T[rr * IMG_W + gx];
        }
        vs01 = add2(vs01, pk2(p, t));
        vs23 = fmaf(p, p, fmaf(t, t, vs23));
        vs4  = fmaf(p, t, vs4);
    }

    // ---------- horizontal-pass identity: 8 rows x 32 segments of 8 ----------
    const int hrow = threadIdx.x & (CHUNK - 1);   // 0..7
    const int hseg = threadIdx.x >> 3;            // 0..31
    const int xs = hseg * 8;
    const bool segvalid = (xs < outw);
    const int nvalid = segvalid ? min(8, outw - xs) : 0;

    float acc = 0.f;
    const float KK   = 1.0f / 121.0f;
    const float TWOK = 2.0f / 121.0f;
    const float K2C  = KK * KK;
    const float TK2  = 2.0f * K2C;
    const float C12  = C1F + C2F;

    const int hbase = hrow * VS2 + xs;            // even (VS2 even, xs mult of 8)

    for (int ch = 0; ch < NCHUNKS; ++ch) {
        const int rbase = r0 + ch * CHUNK;

        // ===== vertical pass: CHUNK rows of packed box-column sums =====
        #pragma unroll
        for (int i = 0; i < CHUNK; ++i) {
            const int r = rbase + i;
            {   // incoming row r+5
                const int rr = r + HALO;
                float p = 0.f, t = 0.f;
                if (colin && rr < IMG_H) {
                    p = P[rr * IMG_W + gx];
                    t = T[rr * IMG_W + gx];
                }
                vs01 = add2(vs01, pk2(p, t));
                vs23 = fmaf(p, p, fmaf(t, t, vs23));
                vs4  = fmaf(p, t, vs4);
            }
            if (cvalid) {
                sm64[i * VS2 + c]          = vs01;             // STS.64
                sm64[A234_U + i * VS2 + c] = pk2(vs23, vs4);   // STS.64
            }
            {   // outgoing row r-5 (L1-resident reload)
                const int ro = r - HALO;
                float p = 0.f, t = 0.f;
                if (colin && ro >= 0) {
                    p = P[ro * IMG_W + gx];
                    t = T[ro * IMG_W + gx];
                }
                vs01 = fma2(pk2(p, t), NEG1_X2, vs01);
                vs23 = fmaf(-p, p, fmaf(-t, t, vs23));
                vs4  = fmaf(-p, t, vs4);
            }
        }
        __syncthreads();

        // ===== horizontal pass: two packed sliding-window passes =====
        if (segvalid) {
            float numA[8], denF[8];

            // Pass A: (Sp, St) -> n1 = 2k^2*Sp*St + C1 ; d1 = k^2*(Sp^2+St^2) + C1
            {
                const ulonglong2* __restrict__ b01 =
                    reinterpret_cast<const ulonglong2*>(sm64 + hbase);
                unsigned long long e[18];
                #pragma unroll
                for (int k = 0; k < 9; ++k) {       // LDS.128, conflict-free
                    ulonglong2 u = b01[k];
                    e[2 * k] = u.x; e[2 * k + 1] = u.y;
                }
                unsigned long long S = e[0];
                #pragma unroll
                for (int k = 1; k < WIN; ++k) S = add2(S, e[k]);
                #pragma unroll
                for (int j = 0; j < 8; ++j) {
                    float sp, st; upk2(S, sp, st);
                    float ab = sp * st;
                    float V  = fmaf(sp, sp, st * st);
                    numA[j] = fmaf(TK2, ab, C1F);
                    denF[j] = fmaf(K2C, V, C1F);
                    if (j < 7) {
                        S = add2(S, e[j + WIN]);
                        S = fma2(e[j], NEG1_X2, S);
                    }
                }
            }
            // Pass BC: (Sqq, Spt) -> n2 = 2k*Spt + C12 - n1 ; d2 = k*Sqq + C12 - d1
            {
                const ulonglong2* __restrict__ b234 =
                    reinterpret_cast<const ulonglong2*>(sm64 + A234_U + hbase);
                unsigned long long e[18];
                #pragma unroll
                for (int k = 0; k < 9; ++k) {
                    ulonglong2 u = b234[k];
                    e[2 * k] = u.x; e[2 * k + 1] = u.y;
                }
                unsigned long long S = e[0];
                #pragma unroll
                for (int k = 1; k < WIN; ++k) S = add2(S, e[k]);
                #pragma unroll
                for (int j = 0; j < 8; ++j) {
                    float sqq, spt; upk2(S, sqq, spt);
                    float n1 = numA[j], d1 = denF[j];
                    float n2 = fmaf(TWOK, spt, C12 - n1);
                    float d2 = fmaf(KK, sqq, C12 - d1);
                    float r = __fdividef(n1 * n2, d1 * d2);
                    if (j < nvalid) acc += r;       // OOB windows masked here
                    if (j < 7) {
                        S = add2(S, e[j + WIN]);
                        S = fma2(e[j], NEG1_X2, S);
                    }
                }
            }
        }
        __syncthreads();
    }

    // ---------- deterministic block reduction ----------
    smem[threadIdx.x] = acc;
    __syncthreads();
    #pragma unroll
    for (int off = NTHREADS / 2; off > 0; off >>= 1) {
        if (threadIdx.x < off) smem[threadIdx.x] += smem[threadIdx.x + off];
        __syncthreads();
    }

    // ---------- fused finalize: last block reduces all partials ----------
    __shared__ bool s_last;
    if (threadIdx.x == 0) {
        g_partials[b] = smem[0];
        __threadfence();
        unsigned int n = atomicAdd(&g_count, 1u);
        s_last = (n == (unsigned int)(N_BLOCKS - 1));
    }
    __syncthreads();
    if (s_last) {
        double* sd = reinterpret_cast<double*>(smem);
        if (threadIdx.x < 128) {
            double s = 0.0;
            if (threadIdx.x < 96) {
                #pragma unroll
                for (int q = 0; q < 9; ++q)      // 96 * 9 = 864, fixed order
                    s += (double)g_partials[threadIdx.x * 9 + q];
            }
            sd[threadIdx.x] = s;
        }
        __syncthreads();
        #pragma unroll
        for (int off = 64; off > 0; off >>= 1) {
            if (threadIdx.x < off) sd[threadIdx.x] += sd[threadIdx.x + off];
            __syncthreads();
        }
        if (threadIdx.x == 0) {
            const double n = (double)N_PLANES * IMG_H * IMG_W;   // 23,592,960
            out[0] = (float)(1.0 - sd[0] / n);
            g_count = 0u;                         // reset for next graph replay
        }
    }
}

extern "C" void kernel_launch(void* const* d_in, const int* in_sizes, int n_in,
                              void* d_out, int out_size) {
    const float* pred = (const float*)d_in[0];
    const float* targ = (const float*)d_in[1];
    float* out = (float*)d_out;

    cudaFuncSetAttribute(ssim_main, cudaFuncAttributeMaxDynamicSharedMemorySize,
                         SMEM_BYTES);
    ssim_main<<<N_BLOCKS, NTHREADS, SMEM_BYTES>>>(pred, targ, out);
}